// round 15
// baseline (speedup 1.0000x reference)
#include <cuda_runtime.h>
#include <cuda_fp16.h>
#include <cstdint>
#include <cstddef>

#define NTOK 2048
#define DIN  1024
#define DHID 4096
#define DOUT 1024
#define NEXP 8
#define CAP  2048

// ---------------- scratch (static device globals; no allocs allowed) ----------------
__device__ int    g_cnt[NEXP];
__device__ int    g_tok_of_row[NEXP * CAP];
__device__ int    g_slot_row[NTOK * 2];
__device__ float  g_slot_w[NTOK * 2];
__device__ __half g_X16[(size_t)NTOK * DIN];          // fp16 x
__device__ __half g_W1h[(size_t)NEXP * DHID * DIN];   // fp16 W1 (64 MB)
__device__ __half g_W2h[(size_t)NEXP * DOUT * DHID];  // fp16 W2 (64 MB)
__device__ __half g_H16[(size_t)NEXP * CAP * DHID];   // fp16 H  (128 MB)
__device__ __half g_Y16[(size_t)NEXP * CAP * DOUT];   // fp16 Y  (32 MB)

// ---------------- helpers ----------------
__device__ __forceinline__ void cp16(uint32_t saddr, const void* gaddr) {
    asm volatile("cp.async.cg.shared.global [%0], [%1], 16;" :: "r"(saddr), "l"(gaddr));
}

__device__ __forceinline__ void ldsm4(uint32_t r[4], uint32_t addr) {
    asm volatile("ldmatrix.sync.aligned.m8n8.x4.shared.b16 {%0,%1,%2,%3}, [%4];"
                 : "=r"(r[0]), "=r"(r[1]), "=r"(r[2]), "=r"(r[3]) : "r"(addr));
}

__device__ __forceinline__ void mma16(float c[4], const uint32_t a[4],
                                      uint32_t b0, uint32_t b1) {
    asm volatile(
        "mma.sync.aligned.m16n8k16.row.col.f32.f16.f16.f32 "
        "{%0,%1,%2,%3},{%4,%5,%6,%7},{%8,%9},{%0,%1,%2,%3};"
        : "+f"(c[0]), "+f"(c[1]), "+f"(c[2]), "+f"(c[3])
        : "r"(a[0]), "r"(a[1]), "r"(a[2]), "r"(a[3]), "r"(b0), "r"(b1));
}

__device__ __forceinline__ void conv4(const float* __restrict__ src,
                                      __half* __restrict__ dst, int i) {
    float4 v = ((const float4*)src)[i];
    __half2 lo = __floats2half2_rn(v.x, v.y);
    __half2 hi = __floats2half2_rn(v.z, v.w);
    uint2 pk;
    pk.x = *reinterpret_cast<uint32_t*>(&lo);
    pk.y = *reinterpret_cast<uint32_t*>(&hi);
    ((uint2*)dst)[i] = pk;
}

// ---------------- kernel 0: zero counters ----------------
__global__ void init_kernel() {
    if (threadIdx.x < NEXP) g_cnt[threadIdx.x] = 0;
}

// ---------------- kernel 1: gate + routing, with x/W1 conversion blocks fused ------
// 1024 blocks of 256 threads: bid%4==0 -> gate (256 blocks); else conversion (768).
__global__ void gate_conv_kernel(const float* __restrict__ x,
                                 const float* __restrict__ gw,
                                 const float* __restrict__ gb,
                                 const float* __restrict__ W1) {
    const int bid = blockIdx.x;
    const int t = threadIdx.x;

    if (bid % 4 != 0) {
        const int cb = bid - bid / 4 - 1;          // 0..767 consecutive conv index
        const int nthr = 768 * 256;
        const int tid0 = cb * 256 + t;
        for (int i = tid0; i < NTOK * DIN / 4; i += nthr) conv4(x, g_X16, i);
        for (int i = tid0; i < NEXP * DHID * DIN / 4; i += nthr) conv4(W1, g_W1h, i);
        return;
    }

    // ---- gate block ----
    __shared__ float sgw[NEXP * DIN];  // 32 KB
    for (int i = t; i < NEXP * DIN / 4; i += 256)
        ((float4*)sgw)[i] = ((const float4*)gw)[i];
    __syncthreads();

    const int warp = t >> 5, lane = t & 31;
    const int n = (bid / 4) * 8 + warp;

    float acc[NEXP];
#pragma unroll
    for (int e = 0; e < NEXP; e++) acc[e] = 0.f;

    const float* xr = x + (size_t)n * DIN;
    for (int kk = 0; kk < DIN; kk += 32) {
        float xv = xr[kk + lane];
#pragma unroll
        for (int e = 0; e < NEXP; e++)
            acc[e] = fmaf(xv, sgw[e * DIN + kk + lane], acc[e]);
    }
#pragma unroll
    for (int off = 16; off; off >>= 1) {
#pragma unroll
        for (int e = 0; e < NEXP; e++)
            acc[e] += __shfl_xor_sync(0xffffffffu, acc[e], off);
    }

    if (lane == 0) {
        float lg[NEXP];
#pragma unroll
        for (int e = 0; e < NEXP; e++) lg[e] = acc[e] + gb[e];
        int e0 = 0;
#pragma unroll
        for (int e = 1; e < NEXP; e++) if (lg[e] > lg[e0]) e0 = e;
        int e1 = (e0 == 0) ? 1 : 0;
#pragma unroll
        for (int e = 0; e < NEXP; e++) if (e != e0 && lg[e] > lg[e1]) e1 = e;

        float z  = expf(lg[e1] - lg[e0]);
        float w0 = 1.f / (1.f + z);
        float w1 = z / (1.f + z);

        int s0 = atomicAdd(&g_cnt[e0], 1);
        int s1 = atomicAdd(&g_cnt[e1], 1);
        int r0 = e0 * CAP + s0;
        int r1 = e1 * CAP + s1;
        g_tok_of_row[r0] = n;
        g_tok_of_row[r1] = n;
        g_slot_row[2 * n]     = r0;
        g_slot_row[2 * n + 1] = r1;
        g_slot_w[2 * n]     = w0;
        g_slot_w[2 * n + 1] = w1;
    }
}

// ---------------- kernels 2/3: expert GEMMs (fp16 mma.sync m16n8k16) ----------------
// MODE 1: H16 = fp16( relu( gather(X16) @ W1h[e]^T + b1[e] ) )   (K=1024, N=4096)
//         Every CTA converts a static 2048-float4 chunk of W2 fp32->fp16:
//         active CTAs spread it 1 conv4/thread per k-tile (kt<8) so each load
//         hides under that k-tile's tensor phase; inactive (m-tail) CTAs burst
//         it in their otherwise-wasted slot. gemm2 starts after completion.
// MODE 2: Y16 = fp16( H16 @ W2h[e]^T + b2[e] )                   (K=4096, N=1024)
// Padding skip: on a partial m-tile with nact<=64, the wm=1 warps (all junk)
// skip ldsm/mma/epilogue but still produce cp.asyncs and sync.
// Block 128x128xBK64, 256 threads (2x4 warps, 64x32 warp tiles), 3-stage cp.async.
#define SM_PITCH_H 72                            // halves per smem row (144 B = 9*16)
#define STAGES     3
#define STAGE_BYT  (128 * SM_PITCH_H * 2)        // 18432 bytes per 128x64 fp16 tile
#define SMEM_BYTES (STAGES * 2 * STAGE_BYT)      // 110592 bytes
#define W2_CHUNK   2048                          // float4 per CTA (4096 CTAs cover 8.4M)

template <int MODE>
__global__ void __launch_bounds__(256, 2) moe_gemm(const float* __restrict__ bias,
                                                   const float* __restrict__ W2f) {
    constexpr int KD = (MODE == 1) ? DIN : DHID;
    constexpr int ND = (MODE == 1) ? DHID : DOUT;
    constexpr int KT = KD / 64;

    const int e  = blockIdx.z;
    const int m0 = blockIdx.y * 128;
    const int n0 = blockIdx.x * 128;
    const int cnt = g_cnt[e];
    const int t = threadIdx.x;

    // static W2 conversion chunk for this CTA (MODE 1 only)
    const int cbase = (MODE == 1)
        ? (blockIdx.x + 32 * (blockIdx.y + 16 * blockIdx.z)) * W2_CHUNK + t
        : 0;

    if (m0 >= cnt) {
        if (MODE == 1) {
#pragma unroll
            for (int k = 0; k < W2_CHUNK / 256; k++)
                conv4(W2f, g_W2h, cbase + k * 256);
        }
        return;
    }

    extern __shared__ char smc[];
    const uint32_t smbase = (uint32_t)__cvta_generic_to_shared(smc);
    const int lane = t & 31, warp = t >> 5;
    const int wm = warp >> 2, wn = warp & 3;         // 2 x 4 warp grid, 64x32 tiles

    // padding skip: upper warp-half is all-junk when this partial tile has <=64 rows
    const int nact = cnt - m0;
    const bool consume = (wm == 0) || (nact > 64);

    const __half* Wh = (MODE == 1) ? g_W1h : g_W2h;

    // ---- producer: 4 16B-chunks per thread per operand ----
    const __half* gA[4];
    const __half* gB[4];
    uint32_t soff[4];
#pragma unroll
    for (int j = 0; j < 4; j++) {
        int i = t + 256 * j;          // chunk index: 8 chunks per row
        int row = i >> 3;             // 0..127
        int col = (i & 7) * 8;        // halves: 0..56
        if (MODE == 1) {
            int r = m0 + row;
            int tok = (r < cnt) ? g_tok_of_row[e * CAP + r] : g_tok_of_row[e * CAP];
            gA[j] = g_X16 + (size_t)tok * KD + col;
        } else {
            gA[j] = g_H16 + (size_t)(e * CAP + m0 + row) * KD + col;
        }
        gB[j] = Wh + ((size_t)e * ND + n0 + row) * KD + col;
        soff[j] = (uint32_t)(row * SM_PITCH_H + col) * 2u;
    }

    // ---- ldmatrix base addresses: row = base + (lane&15), colByte = (lane>>4)*16 ----
    const uint32_t lrow = (uint32_t)(lane & 15);
    const uint32_t lcol = (uint32_t)((lane >> 4) * 16);
    const uint32_t aAddr0 = smbase +
        ((uint32_t)(wm * 64) + lrow) * (SM_PITCH_H * 2) + lcol;
    const uint32_t bAddr0 = smbase + (uint32_t)(STAGES * STAGE_BYT) +
        ((uint32_t)(wn * 32) + lrow) * (SM_PITCH_H * 2) + lcol;

    float c[4][4][4];
#pragma unroll
    for (int am = 0; am < 4; am++)
#pragma unroll
        for (int bn = 0; bn < 4; bn++)
#pragma unroll
            for (int i = 0; i < 4; i++) c[am][bn][i] = 0.f;

    auto issue = [&](int kt, int s) {
        const int kof = kt * 64;
        const uint32_t ab = smbase + (uint32_t)(s * STAGE_BYT);
        const uint32_t bb = smbase + (uint32_t)((STAGES + s) * STAGE_BYT);
#pragma unroll
        for (int j = 0; j < 4; j++) cp16(ab + soff[j], gA[j] + kof);
#pragma unroll
        for (int j = 0; j < 4; j++) cp16(bb + soff[j], gB[j] + kof);
        asm volatile("cp.async.commit_group;");
    };

    // prologue: stages 0,1 in flight (no conversion burst here — spread over k-tiles)
    issue(0, 0);
    issue(1, 1);
    asm volatile("cp.async.wait_group 1;");
    __syncthreads();

    for (int kt = 0; kt < KT; kt++) {
        const int s = kt % STAGES;
        if (kt + 2 < KT) issue(kt + 2, (kt + 2) % STAGES);
        else asm volatile("cp.async.commit_group;");   // keep group accounting

        // one thin slice of W2 conversion per k-tile, hidden under tensor work
        if (MODE == 1 && kt < W2_CHUNK / 256)
            conv4(W2f, g_W2h, cbase + kt * 256);

        if (consume) {
            const uint32_t aS = aAddr0 + (uint32_t)(s * STAGE_BYT);
            const uint32_t bS = bAddr0 + (uint32_t)(s * STAGE_BYT);

#pragma unroll
            for (int sl = 0; sl < 4; sl++) {              // 4 k16-slices per 64-K tile
                const uint32_t ko = (uint32_t)(sl * 32);  // 16 halves = 32 bytes
                uint32_t a[4][4];
#pragma unroll
                for (int am = 0; am < 4; am++)
                    ldsm4(a[am], aS + am * (16 * SM_PITCH_H * 2) + ko);
                uint32_t b0[4], b1[4];
                ldsm4(b0, bS + ko);
                ldsm4(b1, bS + 16 * (SM_PITCH_H * 2) + ko);
#pragma unroll
                for (int am = 0; am < 4; am++) {
                    mma16(c[am][0], a[am], b0[0], b0[2]);
                    mma16(c[am][1], a[am], b0[1], b0[3]);
                    mma16(c[am][2], a[am], b1[0], b1[2]);
                    mma16(c[am][3], a[am], b1[1], b1[3]);
                }
            }
        }

        asm volatile("cp.async.wait_group 1;");
        __syncthreads();
    }

    // ---- epilogue (skipped by all-junk warp halves) ----
    if (consume) {
        const int grp = lane >> 2, tig = lane & 3;
        const float* bv = bias + (size_t)e * ND + n0;
#pragma unroll
        for (int bn = 0; bn < 4; bn++) {
            const int cg = wn * 32 + bn * 8 + tig * 2;
            const float b0v = bv[cg], b1v = bv[cg + 1];
#pragma unroll
            for (int am = 0; am < 4; am++) {
                const int rl = wm * 64 + am * 16 + grp;
                float v0 = c[am][bn][0] + b0v;
                float v1 = c[am][bn][1] + b1v;
                float v2 = c[am][bn][2] + b0v;
                float v3 = c[am][bn][3] + b1v;
                const size_t base0 = (size_t)(e * CAP + m0 + rl) * ND + n0 + cg;
                const size_t base1 = (size_t)(e * CAP + m0 + rl + 8) * ND + n0 + cg;
                if (MODE == 1) {   // relu then fp16 for GEMM2's A operand
                    __half2 h0 = __floats2half2_rn(fmaxf(v0, 0.f), fmaxf(v1, 0.f));
                    __half2 h1 = __floats2half2_rn(fmaxf(v2, 0.f), fmaxf(v3, 0.f));
                    *reinterpret_cast<uint32_t*>(&g_H16[base0]) = *reinterpret_cast<uint32_t*>(&h0);
                    *reinterpret_cast<uint32_t*>(&g_H16[base1]) = *reinterpret_cast<uint32_t*>(&h1);
                } else {           // fp16 Y (combine upconverts)
                    __half2 h0 = __floats2half2_rn(v0, v1);
                    __half2 h1 = __floats2half2_rn(v2, v3);
                    *reinterpret_cast<uint32_t*>(&g_Y16[base0]) = *reinterpret_cast<uint32_t*>(&h0);
                    *reinterpret_cast<uint32_t*>(&g_Y16[base1]) = *reinterpret_cast<uint32_t*>(&h1);
                }
            }
        }
    }
}

// ---------------- kernel 4: weighted combine (fp16 Y -> fp32 out) ----------------
__global__ void combine_kernel(float* __restrict__ out) {
    const int n = blockIdx.x, t = threadIdx.x;   // 256 threads, 4 cols each
    const int r0 = g_slot_row[2 * n], r1 = g_slot_row[2 * n + 1];
    const float w0 = g_slot_w[2 * n], w1 = g_slot_w[2 * n + 1];
    const uint2 pa = ((const uint2*)(g_Y16 + (size_t)r0 * DOUT))[t];
    const uint2 pb = ((const uint2*)(g_Y16 + (size_t)r1 * DOUT))[t];
    const __half2 a0 = *reinterpret_cast<const __half2*>(&pa.x);
    const __half2 a1 = *reinterpret_cast<const __half2*>(&pa.y);
    const __half2 b0 = *reinterpret_cast<const __half2*>(&pb.x);
    const __half2 b1 = *reinterpret_cast<const __half2*>(&pb.y);
    const float2 fa0 = __half22float2(a0), fa1 = __half22float2(a1);
    const float2 fb0 = __half22float2(b0), fb1 = __half22float2(b1);
    float4 o;
    o.x = w0 * fa0.x + w1 * fb0.x;
    o.y = w0 * fa0.y + w1 * fb0.y;
    o.z = w0 * fa1.x + w1 * fb1.x;
    o.w = w0 * fa1.y + w1 * fb1.y;
    reinterpret_cast<float4*>(out + (size_t)n * DOUT)[t] = o;
}

// ---------------- launch ----------------
extern "C" void kernel_launch(void* const* d_in, const int* in_sizes, int n_in,
                              void* d_out, int out_size) {
    const float* x  = (const float*)d_in[0];
    const float* gw = (const float*)d_in[1];
    const float* gb = (const float*)d_in[2];
    const float* W1 = (const float*)d_in[3];
    const float* b1 = (const float*)d_in[4];
    const float* W2 = (const float*)d_in[5];
    const float* b2 = (const float*)d_in[6];
    float* out = (float*)d_out;

    cudaFuncSetAttribute(moe_gemm<1>, cudaFuncAttributeMaxDynamicSharedMemorySize, SMEM_BYTES);
    cudaFuncSetAttribute(moe_gemm<2>, cudaFuncAttributeMaxDynamicSharedMemorySize, SMEM_BYTES);

    init_kernel<<<1, 32>>>();
    gate_conv_kernel<<<1024, 256>>>(x, gw, gb, W1);
    moe_gemm<1><<<dim3(DHID / 128, CAP / 128, NEXP), 256, SMEM_BYTES>>>(b1, W2);
    moe_gemm<2><<<dim3(DOUT / 128, CAP / 128, NEXP), 256, SMEM_BYTES>>>(b2, nullptr);
    combine_kernel<<<NTOK, 256>>>(out);
}

// round 16
// speedup vs baseline: 1.0193x; 1.0193x over previous
#include <cuda_runtime.h>
#include <cuda_fp16.h>
#include <cstdint>
#include <cstddef>

#define NTOK 2048
#define DIN  1024
#define DHID 4096
#define DOUT 1024
#define NEXP 8
#define CAP  2048

// ---------------- scratch (static device globals; no allocs allowed) ----------------
__device__ int    g_cnt[NEXP];
__device__ int    g_tok_of_row[NEXP * CAP];
__device__ int    g_slot_row[NTOK * 2];
__device__ float  g_slot_w[NTOK * 2];
__device__ __half g_X16[(size_t)NTOK * DIN];          // fp16 x
__device__ __half g_W1h[(size_t)NEXP * DHID * DIN];   // fp16 W1 (64 MB)
__device__ __half g_W2h[(size_t)NEXP * DOUT * DHID];  // fp16 W2 (64 MB)
__device__ __half g_H16[(size_t)NEXP * CAP * DHID];   // fp16 H  (128 MB)
__device__ __half g_Y16[(size_t)NEXP * CAP * DOUT];   // fp16 Y  (32 MB)

// ---------------- helpers ----------------
__device__ __forceinline__ void cp16(uint32_t saddr, const void* gaddr) {
    asm volatile("cp.async.cg.shared.global [%0], [%1], 16;" :: "r"(saddr), "l"(gaddr));
}

__device__ __forceinline__ void ldsm4(uint32_t r[4], uint32_t addr) {
    asm volatile("ldmatrix.sync.aligned.m8n8.x4.shared.b16 {%0,%1,%2,%3}, [%4];"
                 : "=r"(r[0]), "=r"(r[1]), "=r"(r[2]), "=r"(r[3]) : "r"(addr));
}

__device__ __forceinline__ void mma16(float c[4], const uint32_t a[4],
                                      uint32_t b0, uint32_t b1) {
    asm volatile(
        "mma.sync.aligned.m16n8k16.row.col.f32.f16.f16.f32 "
        "{%0,%1,%2,%3},{%4,%5,%6,%7},{%8,%9},{%0,%1,%2,%3};"
        : "+f"(c[0]), "+f"(c[1]), "+f"(c[2]), "+f"(c[3])
        : "r"(a[0]), "r"(a[1]), "r"(a[2]), "r"(a[3]), "r"(b0), "r"(b1));
}

__device__ __forceinline__ void conv4(const float* __restrict__ src,
                                      __half* __restrict__ dst, int i) {
    float4 v = ((const float4*)src)[i];
    __half2 lo = __floats2half2_rn(v.x, v.y);
    __half2 hi = __floats2half2_rn(v.z, v.w);
    uint2 pk;
    pk.x = *reinterpret_cast<uint32_t*>(&lo);
    pk.y = *reinterpret_cast<uint32_t*>(&hi);
    ((uint2*)dst)[i] = pk;
}

// ---------------- kernel 0: zero counters ----------------
__global__ void init_kernel() {
    if (threadIdx.x < NEXP) g_cnt[threadIdx.x] = 0;
}

// ---------------- kernel 1: gate + routing, with x/W1 conversion blocks fused ------
// 1024 blocks of 256 threads: bid%4==0 -> gate (256 blocks); else conversion (768).
__global__ void gate_conv_kernel(const float* __restrict__ x,
                                 const float* __restrict__ gw,
                                 const float* __restrict__ gb,
                                 const float* __restrict__ W1) {
    const int bid = blockIdx.x;
    const int t = threadIdx.x;

    if (bid % 4 != 0) {
        const int cb = bid - bid / 4 - 1;          // 0..767 consecutive conv index
        const int nthr = 768 * 256;
        const int tid0 = cb * 256 + t;
        for (int i = tid0; i < NTOK * DIN / 4; i += nthr) conv4(x, g_X16, i);
        for (int i = tid0; i < NEXP * DHID * DIN / 4; i += nthr) conv4(W1, g_W1h, i);
        return;
    }

    // ---- gate block ----
    __shared__ float sgw[NEXP * DIN];  // 32 KB
    for (int i = t; i < NEXP * DIN / 4; i += 256)
        ((float4*)sgw)[i] = ((const float4*)gw)[i];
    __syncthreads();

    const int warp = t >> 5, lane = t & 31;
    const int n = (bid / 4) * 8 + warp;

    float acc[NEXP];
#pragma unroll
    for (int e = 0; e < NEXP; e++) acc[e] = 0.f;

    const float* xr = x + (size_t)n * DIN;
    for (int kk = 0; kk < DIN; kk += 32) {
        float xv = xr[kk + lane];
#pragma unroll
        for (int e = 0; e < NEXP; e++)
            acc[e] = fmaf(xv, sgw[e * DIN + kk + lane], acc[e]);
    }
#pragma unroll
    for (int off = 16; off; off >>= 1) {
#pragma unroll
        for (int e = 0; e < NEXP; e++)
            acc[e] += __shfl_xor_sync(0xffffffffu, acc[e], off);
    }

    if (lane == 0) {
        float lg[NEXP];
#pragma unroll
        for (int e = 0; e < NEXP; e++) lg[e] = acc[e] + gb[e];
        int e0 = 0;
#pragma unroll
        for (int e = 1; e < NEXP; e++) if (lg[e] > lg[e0]) e0 = e;
        int e1 = (e0 == 0) ? 1 : 0;
#pragma unroll
        for (int e = 0; e < NEXP; e++) if (e != e0 && lg[e] > lg[e1]) e1 = e;

        float z  = expf(lg[e1] - lg[e0]);
        float w0 = 1.f / (1.f + z);
        float w1 = z / (1.f + z);

        int s0 = atomicAdd(&g_cnt[e0], 1);
        int s1 = atomicAdd(&g_cnt[e1], 1);
        int r0 = e0 * CAP + s0;
        int r1 = e1 * CAP + s1;
        g_tok_of_row[r0] = n;
        g_tok_of_row[r1] = n;
        g_slot_row[2 * n]     = r0;
        g_slot_row[2 * n + 1] = r1;
        g_slot_w[2 * n]     = w0;
        g_slot_w[2 * n + 1] = w1;
    }
}

// ---------------- kernels 2/3: expert GEMMs (fp16 mma.sync m16n8k16) ----------------
// MODE 1: H16 = fp16( relu( gather(X16) @ W1h[e]^T + b1[e] ) )   (K=1024, N=4096)
//         Every CTA also converts a static 2048-float4 chunk of W2 (fp32->fp16):
//         inactive (m-tail) CTAs in their otherwise-wasted slot, active CTAs in
//         the cp.async prologue shadow. gemm2 starts after this kernel completes.
// MODE 2: Y16 = fp16( H16 @ W2h[e]^T + b2[e] )                   (K=4096, N=1024)
// Padding skip: on a partial m-tile with nact<=64, the wm=1 warps (rows 64..127,
// all junk) skip ldsm/mma/epilogue but still produce cp.asyncs and sync.
// Block 128x128xBK64, 256 threads (2x4 warps, 64x32 warp tiles), 3-stage cp.async.
#define SM_PITCH_H 72                            // halves per smem row (144 B = 9*16)
#define STAGES     3
#define STAGE_BYT  (128 * SM_PITCH_H * 2)        // 18432 bytes per 128x64 fp16 tile
#define SMEM_BYTES (STAGES * 2 * STAGE_BYT)      // 110592 bytes
#define W2_CHUNK   2048                          // float4 per CTA (4096 CTAs cover 8.4M)

template <int MODE>
__global__ void __launch_bounds__(256, 2) moe_gemm(const float* __restrict__ bias,
                                                   const float* __restrict__ W2f) {
    constexpr int KD = (MODE == 1) ? DIN : DHID;
    constexpr int ND = (MODE == 1) ? DHID : DOUT;
    constexpr int KT = KD / 64;

    const int e  = blockIdx.z;
    const int m0 = blockIdx.y * 128;
    const int n0 = blockIdx.x * 128;
    const int cnt = g_cnt[e];
    const int t = threadIdx.x;

    // static W2 conversion chunk for this CTA (MODE 1 only)
    const int cbase = (MODE == 1)
        ? (blockIdx.x + 32 * (blockIdx.y + 16 * blockIdx.z)) * W2_CHUNK + t
        : 0;

    if (m0 >= cnt) {
        if (MODE == 1) {
#pragma unroll
            for (int k = 0; k < W2_CHUNK / 256; k++)
                conv4(W2f, g_W2h, cbase + k * 256);
        }
        return;
    }

    extern __shared__ char smc[];
    const uint32_t smbase = (uint32_t)__cvta_generic_to_shared(smc);
    const int lane = t & 31, warp = t >> 5;
    const int wm = warp >> 2, wn = warp & 3;         // 2 x 4 warp grid, 64x32 tiles

    // padding skip: upper warp-half is all-junk when this partial tile has <=64 rows
    const int nact = cnt - m0;
    const bool consume = (wm == 0) || (nact > 64);

    const __half* Wh = (MODE == 1) ? g_W1h : g_W2h;

    // ---- producer: 4 16B-chunks per thread per operand ----
    const __half* gA[4];
    const __half* gB[4];
    uint32_t soff[4];
#pragma unroll
    for (int j = 0; j < 4; j++) {
        int i = t + 256 * j;          // chunk index: 8 chunks per row
        int row = i >> 3;             // 0..127
        int col = (i & 7) * 8;        // halves: 0..56
        if (MODE == 1) {
            int r = m0 + row;
            int tok = (r < cnt) ? g_tok_of_row[e * CAP + r] : g_tok_of_row[e * CAP];
            gA[j] = g_X16 + (size_t)tok * KD + col;
        } else {
            gA[j] = g_H16 + (size_t)(e * CAP + m0 + row) * KD + col;
        }
        gB[j] = Wh + ((size_t)e * ND + n0 + row) * KD + col;
        soff[j] = (uint32_t)(row * SM_PITCH_H + col) * 2u;
    }

    // ---- ldmatrix base addresses: row = base + (lane&15), colByte = (lane>>4)*16 ----
    const uint32_t lrow = (uint32_t)(lane & 15);
    const uint32_t lcol = (uint32_t)((lane >> 4) * 16);
    const uint32_t aAddr0 = smbase +
        ((uint32_t)(wm * 64) + lrow) * (SM_PITCH_H * 2) + lcol;
    const uint32_t bAddr0 = smbase + (uint32_t)(STAGES * STAGE_BYT) +
        ((uint32_t)(wn * 32) + lrow) * (SM_PITCH_H * 2) + lcol;

    float c[4][4][4];
#pragma unroll
    for (int am = 0; am < 4; am++)
#pragma unroll
        for (int bn = 0; bn < 4; bn++)
#pragma unroll
            for (int i = 0; i < 4; i++) c[am][bn][i] = 0.f;

    auto issue = [&](int kt, int s) {
        const int kof = kt * 64;
        const uint32_t ab = smbase + (uint32_t)(s * STAGE_BYT);
        const uint32_t bb = smbase + (uint32_t)((STAGES + s) * STAGE_BYT);
#pragma unroll
        for (int j = 0; j < 4; j++) cp16(ab + soff[j], gA[j] + kof);
#pragma unroll
        for (int j = 0; j < 4; j++) cp16(bb + soff[j], gB[j] + kof);
        asm volatile("cp.async.commit_group;");
    };

    // prologue: stages 0,1 in flight; W2 conversion rides in the wait shadow
    issue(0, 0);
    issue(1, 1);
    if (MODE == 1) {
#pragma unroll
        for (int k = 0; k < W2_CHUNK / 256; k++)
            conv4(W2f, g_W2h, cbase + k * 256);
    }
    asm volatile("cp.async.wait_group 1;");
    __syncthreads();

    for (int kt = 0; kt < KT; kt++) {
        const int s = kt % STAGES;
        if (kt + 2 < KT) issue(kt + 2, (kt + 2) % STAGES);
        else asm volatile("cp.async.commit_group;");   // keep group accounting

        if (consume) {
            const uint32_t aS = aAddr0 + (uint32_t)(s * STAGE_BYT);
            const uint32_t bS = bAddr0 + (uint32_t)(s * STAGE_BYT);

#pragma unroll
            for (int sl = 0; sl < 4; sl++) {              // 4 k16-slices per 64-K tile
                const uint32_t ko = (uint32_t)(sl * 32);  // 16 halves = 32 bytes
                uint32_t a[4][4];
#pragma unroll
                for (int am = 0; am < 4; am++)
                    ldsm4(a[am], aS + am * (16 * SM_PITCH_H * 2) + ko);
                uint32_t b0[4], b1[4];
                ldsm4(b0, bS + ko);
                ldsm4(b1, bS + 16 * (SM_PITCH_H * 2) + ko);
#pragma unroll
                for (int am = 0; am < 4; am++) {
                    mma16(c[am][0], a[am], b0[0], b0[2]);
                    mma16(c[am][1], a[am], b0[1], b0[3]);
                    mma16(c[am][2], a[am], b1[0], b1[2]);
                    mma16(c[am][3], a[am], b1[1], b1[3]);
                }
            }
        }

        asm volatile("cp.async.wait_group 1;");
        __syncthreads();
    }

    // ---- epilogue (skipped by all-junk warp halves) ----
    if (consume) {
        const int grp = lane >> 2, tig = lane & 3;
        const float* bv = bias + (size_t)e * ND + n0;
#pragma unroll
        for (int bn = 0; bn < 4; bn++) {
            const int cg = wn * 32 + bn * 8 + tig * 2;
            const float b0v = bv[cg], b1v = bv[cg + 1];
#pragma unroll
            for (int am = 0; am < 4; am++) {
                const int rl = wm * 64 + am * 16 + grp;
                float v0 = c[am][bn][0] + b0v;
                float v1 = c[am][bn][1] + b1v;
                float v2 = c[am][bn][2] + b0v;
                float v3 = c[am][bn][3] + b1v;
                const size_t base0 = (size_t)(e * CAP + m0 + rl) * ND + n0 + cg;
                const size_t base1 = (size_t)(e * CAP + m0 + rl + 8) * ND + n0 + cg;
                if (MODE == 1) {   // relu then fp16 for GEMM2's A operand
                    __half2 h0 = __floats2half2_rn(fmaxf(v0, 0.f), fmaxf(v1, 0.f));
                    __half2 h1 = __floats2half2_rn(fmaxf(v2, 0.f), fmaxf(v3, 0.f));
                    *reinterpret_cast<uint32_t*>(&g_H16[base0]) = *reinterpret_cast<uint32_t*>(&h0);
                    *reinterpret_cast<uint32_t*>(&g_H16[base1]) = *reinterpret_cast<uint32_t*>(&h1);
                } else {           // fp16 Y (combine upconverts)
                    __half2 h0 = __floats2half2_rn(v0, v1);
                    __half2 h1 = __floats2half2_rn(v2, v3);
                    *reinterpret_cast<uint32_t*>(&g_Y16[base0]) = *reinterpret_cast<uint32_t*>(&h0);
                    *reinterpret_cast<uint32_t*>(&g_Y16[base1]) = *reinterpret_cast<uint32_t*>(&h1);
                }
            }
        }
    }
}

// ---------------- kernel 4: weighted combine (fp16 Y -> fp32 out) ----------------
__global__ void combine_kernel(float* __restrict__ out) {
    const int n = blockIdx.x, t = threadIdx.x;   // 256 threads, 4 cols each
    const int r0 = g_slot_row[2 * n], r1 = g_slot_row[2 * n + 1];
    const float w0 = g_slot_w[2 * n], w1 = g_slot_w[2 * n + 1];
    const uint2 pa = ((const uint2*)(g_Y16 + (size_t)r0 * DOUT))[t];
    const uint2 pb = ((const uint2*)(g_Y16 + (size_t)r1 * DOUT))[t];
    const __half2 a0 = *reinterpret_cast<const __half2*>(&pa.x);
    const __half2 a1 = *reinterpret_cast<const __half2*>(&pa.y);
    const __half2 b0 = *reinterpret_cast<const __half2*>(&pb.x);
    const __half2 b1 = *reinterpret_cast<const __half2*>(&pb.y);
    const float2 fa0 = __half22float2(a0), fa1 = __half22float2(a1);
    const float2 fb0 = __half22float2(b0), fb1 = __half22float2(b1);
    float4 o;
    o.x = w0 * fa0.x + w1 * fb0.x;
    o.y = w0 * fa0.y + w1 * fb0.y;
    o.z = w0 * fa1.x + w1 * fb1.x;
    o.w = w0 * fa1.y + w1 * fb1.y;
    reinterpret_cast<float4*>(out + (size_t)n * DOUT)[t] = o;
}

// ---------------- launch ----------------
extern "C" void kernel_launch(void* const* d_in, const int* in_sizes, int n_in,
                              void* d_out, int out_size) {
    const float* x  = (const float*)d_in[0];
    const float* gw = (const float*)d_in[1];
    const float* gb = (const float*)d_in[2];
    const float* W1 = (const float*)d_in[3];
    const float* b1 = (const float*)d_in[4];
    const float* W2 = (const float*)d_in[5];
    const float* b2 = (const float*)d_in[6];
    float* out = (float*)d_out;

    cudaFuncSetAttribute(moe_gemm<1>, cudaFuncAttributeMaxDynamicSharedMemorySize, SMEM_BYTES);
    cudaFuncSetAttribute(moe_gemm<2>, cudaFuncAttributeMaxDynamicSharedMemorySize, SMEM_BYTES);

    init_kernel<<<1, 32>>>();
    gate_conv_kernel<<<1024, 256>>>(x, gw, gb, W1);
    moe_gemm<1><<<dim3(DHID / 128, CAP / 128, NEXP), 256, SMEM_BYTES>>>(b1, W2);
    moe_gemm<2><<<dim3(DOUT / 128, CAP / 128, NEXP), 256, SMEM_BYTES>>>(b2, nullptr);
    combine_kernel<<<NTOK, 256>>>(out);
}